// round 12
// baseline (speedup 1.0000x reference)
#include <cuda_runtime.h>

// Upscale2d: 2x zero-insert upsample + 4x4 binomial FIR == separable 2-tap
// polyphase: even (a + 3b)/4, odd (3b + c)/4 per axis.
// x: [8,64,256,256] f32 -> y: [8,64,512,512] f32, zero-padded borders.
//
// Final composition of best-measured ingredients:
//  - RPT=16 (lowest read amplification 1.125x, fewest tile overheads; R3's
//    best raw kernel time)
//  - distance-2 pipelined float2 row loads (2 LDGs in flight; R7's edge)
//  - plain write-back float4 stores (R10: >= .cs)
//  - shuffle-based horizontal combines, lanes 0/31 predicated edge loads.

#define IN_H 256
#define IN_W 256
#define OUT_W 512
#define RPT 16   // input rows per thread

__global__ __launch_bounds__(256) void upscale2d_kernel(
    const float* __restrict__ x, float* __restrict__ y)
{
    const int t    = threadIdx.x & 127;        // owns input cols [2t, 2t+1]
    const int sub  = threadIdx.x >> 7;         // 0/1: row-group within block
    const int g    = blockIdx.x * 2 + sub;     // row group
    const int p    = blockIdx.y;               // plane (N*C)
    const int lane = threadIdx.x & 31;

    const int c0 = 2 * t;
    const float* xp = x + (size_t)p * IN_H * IN_W;
    float*       yp = y + (size_t)p * OUT_W * OUT_W;
    const int r0 = g * RPT;

    const bool edgeL = (lane == 0)  && (c0 >= 1);
    const bool edgeR = (lane == 31) && (c0 + 2 < IN_W);

    // raw row load (zero outside [0, IN_H)); e = cross-warp edge element
    auto loadraw = [&](int r, float& e) -> float2 {
        e = 0.f;
        if (r < 0 || r >= IN_H) return make_float2(0.f, 0.f);
        const float* row = xp + (size_t)r * IN_W;
        if (edgeL) e = __ldg(row + c0 - 1);
        if (edgeR) e = __ldg(row + c0 + 2);
        return *(const float2*)(row + c0);
    };

    // horizontal pre-combines: H = even phase, O = odd phase (2 columns)
    auto comb = [&](float2 c, float e,
                    float& H0, float& O0, float& H1, float& O1) {
        float l  = __shfl_up_sync(0xffffffffu, c.y, 1);   // col c0-1
        float rr = __shfl_down_sync(0xffffffffu, c.x, 1); // col c0+2
        if (lane == 0)  l  = e;
        if (lane == 31) rr = e;
        H0 = l   + 3.f * c.x;  O0 = 3.f * c.x + c.y;
        H1 = c.x + 3.f * c.y;  O1 = 3.f * c.y + rr;
    };

    // prologue: 3 loads issued back-to-back (r0-1, r0, r0+1)
    float ePr, eA, eB;
    float2 rPr = loadraw(r0 - 1, ePr);
    float2 rA  = loadraw(r0,     eA);   // consumed at i=0
    float2 rB  = loadraw(r0 + 1, eB);   // consumed at i=1

    float pH0, pO0, pH1, pO1;
    comb(rPr, ePr, pH0, pO0, pH1, pO1);

    #pragma unroll
    for (int i = 0; i <= RPT; i++) {
        const int r = r0 + i;

        // prefetch row r+2 FIRST (keeps 2 LDGs in flight)
        float eF = 0.f;
        float2 rF = make_float2(0.f, 0.f);
        if (i + 2 <= RPT) rF = loadraw(r + 2, eF);

        // combine current row (loaded 2 iterations ago)
        float cH0, cO0, cH1, cO1;
        comb(rA, eA, cH0, cO0, cH1, cO1);

        // output row 2r-1: vertical odd phase (3*prev + cur) * 1/16
        if (i > 0) {
            float4 v;
            v.x = (3.f * pH0 + cH0) * 0.0625f;
            v.y = (3.f * pO0 + cO0) * 0.0625f;
            v.z = (3.f * pH1 + cH1) * 0.0625f;
            v.w = (3.f * pO1 + cO1) * 0.0625f;
            *(float4*)(yp + (size_t)(2 * r - 1) * OUT_W + 2 * c0) = v;
        }
        // output row 2r: vertical even phase (prev + 3*cur) * 1/16
        if (i < RPT) {
            float4 v;
            v.x = (pH0 + 3.f * cH0) * 0.0625f;
            v.y = (pO0 + 3.f * cO0) * 0.0625f;
            v.z = (pH1 + 3.f * cH1) * 0.0625f;
            v.w = (pO1 + 3.f * cO1) * 0.0625f;
            *(float4*)(yp + (size_t)(2 * r) * OUT_W + 2 * c0) = v;
        }

        pH0 = cH0; pO0 = cO0; pH1 = cH1; pO1 = cO1;
        rA = rB; eA = eB;        // shift the 2-slot buffer
        rB = rF; eB = eF;
    }
}

extern "C" void kernel_launch(void* const* d_in, const int* in_sizes, int n_in,
                              void* d_out, int out_size)
{
    const float* x = (const float*)d_in[0];
    float* y = (float*)d_out;
    int planes = in_sizes[0] / (IN_H * IN_W);            // 512
    dim3 grid(IN_H / (RPT * 2), planes);                 // (8, 512)
    upscale2d_kernel<<<grid, 256>>>(x, y);
}

// round 13
// speedup vs baseline: 1.0724x; 1.0724x over previous
#include <cuda_runtime.h>

// Upscale2d: 2x zero-insert upsample + 4x4 binomial FIR == separable 2-tap
// polyphase: even (a + 3b)/4, odd (3b + c)/4 per axis.
// x: [8,64,256,256] f32 -> y: [8,64,512,512] f32, zero-padded borders.
//
// R10 structure (best so far): 2 cols/thread, RPT=8, rolling vertical
// window, distance-2 pipelined float2 row loads, shuffle horizontal
// combines, plain write-back float4 stores.
// SINGLE CHANGE vs R10: 128-thread CTAs (one worker per CTA) instead of
// 256 — higher residency cap (15 blocks/SM = 60 warps vs 56), independent
// retirement of workers, finer wave tail.

#define IN_H 256
#define IN_W 256
#define OUT_W 512
#define RPT 8   // input rows per thread

__global__ __launch_bounds__(128) void upscale2d_kernel(
    const float* __restrict__ x, float* __restrict__ y)
{
    const int t    = threadIdx.x;              // 0..127: owns cols [2t, 2t+1]
    const int g    = blockIdx.x;               // row group 0..31
    const int p    = blockIdx.y;               // plane (N*C)
    const int lane = threadIdx.x & 31;

    const int c0 = 2 * t;
    const float* xp = x + (size_t)p * IN_H * IN_W;
    float*       yp = y + (size_t)p * OUT_W * OUT_W;
    const int r0 = g * RPT;

    const bool edgeL = (lane == 0)  && (c0 >= 1);
    const bool edgeR = (lane == 31) && (c0 + 2 < IN_W);

    // raw row load (zero outside [0, IN_H)); e = cross-warp edge element
    auto loadraw = [&](int r, float& e) -> float2 {
        e = 0.f;
        if (r < 0 || r >= IN_H) return make_float2(0.f, 0.f);
        const float* row = xp + (size_t)r * IN_W;
        if (edgeL) e = __ldg(row + c0 - 1);
        if (edgeR) e = __ldg(row + c0 + 2);
        return *(const float2*)(row + c0);
    };

    // horizontal pre-combines: H = even phase, O = odd phase (2 columns)
    auto comb = [&](float2 c, float e,
                    float& H0, float& O0, float& H1, float& O1) {
        float l  = __shfl_up_sync(0xffffffffu, c.y, 1);   // col c0-1
        float rr = __shfl_down_sync(0xffffffffu, c.x, 1); // col c0+2
        if (lane == 0)  l  = e;
        if (lane == 31) rr = e;
        H0 = l   + 3.f * c.x;  O0 = 3.f * c.x + c.y;
        H1 = c.x + 3.f * c.y;  O1 = 3.f * c.y + rr;
    };

    // prologue: 3 loads issued back-to-back (r0-1, r0, r0+1)
    float ePr, eA, eB;
    float2 rPr = loadraw(r0 - 1, ePr);
    float2 rA  = loadraw(r0,     eA);   // consumed at i=0
    float2 rB  = loadraw(r0 + 1, eB);   // consumed at i=1

    float pH0, pO0, pH1, pO1;
    comb(rPr, ePr, pH0, pO0, pH1, pO1);

    #pragma unroll
    for (int i = 0; i <= RPT; i++) {
        const int r = r0 + i;

        // prefetch row r+2 FIRST (keeps 2 LDGs in flight)
        float eF = 0.f;
        float2 rF = make_float2(0.f, 0.f);
        if (i + 2 <= RPT) rF = loadraw(r + 2, eF);

        // combine current row (loaded 2 iterations ago)
        float cH0, cO0, cH1, cO1;
        comb(rA, eA, cH0, cO0, cH1, cO1);

        // output row 2r-1: vertical odd phase (3*prev + cur) * 1/16
        if (i > 0) {
            float4 v;
            v.x = (3.f * pH0 + cH0) * 0.0625f;
            v.y = (3.f * pO0 + cO0) * 0.0625f;
            v.z = (3.f * pH1 + cH1) * 0.0625f;
            v.w = (3.f * pO1 + cO1) * 0.0625f;
            *(float4*)(yp + (size_t)(2 * r - 1) * OUT_W + 2 * c0) = v;
        }
        // output row 2r: vertical even phase (prev + 3*cur) * 1/16
        if (i < RPT) {
            float4 v;
            v.x = (pH0 + 3.f * cH0) * 0.0625f;
            v.y = (pO0 + 3.f * cO0) * 0.0625f;
            v.z = (pH1 + 3.f * cH1) * 0.0625f;
            v.w = (pO1 + 3.f * cO1) * 0.0625f;
            *(float4*)(yp + (size_t)(2 * r) * OUT_W + 2 * c0) = v;
        }

        pH0 = cH0; pO0 = cO0; pH1 = cH1; pO1 = cO1;
        rA = rB; eA = eB;        // shift the 2-slot buffer
        rB = rF; eB = eF;
    }
}

extern "C" void kernel_launch(void* const* d_in, const int* in_sizes, int n_in,
                              void* d_out, int out_size)
{
    const float* x = (const float*)d_in[0];
    float* y = (float*)d_out;
    int planes = in_sizes[0] / (IN_H * IN_W);            // 512
    dim3 grid(IN_H / RPT, planes);                       // (32, 512)
    upscale2d_kernel<<<grid, 128>>>(x, y);
}

// round 14
// speedup vs baseline: 1.1099x; 1.0350x over previous
#include <cuda_runtime.h>

// Upscale2d: 2x zero-insert upsample + 4x4 binomial FIR == separable 2-tap
// polyphase: even (a + 3b)/4, odd (3b + c)/4 per axis.
// x: [8,64,256,256] f32 -> y: [8,64,512,512] f32, zero-padded borders.
//
// Minimum-register pipelined configuration: RPT=4, 128-thread CTAs,
// distance-2 pipelined float2 row loads, shuffle horizontal combines,
// plain write-back float4 stores. Boundary-row re-reads across tiles are
// L2 hits (input fits in L2), so small RPT costs no DRAM traffic while
// maximizing resident warps.

#define IN_H 256
#define IN_W 256
#define OUT_W 512
#define RPT 4   // input rows per thread

__global__ __launch_bounds__(128) void upscale2d_kernel(
    const float* __restrict__ x, float* __restrict__ y)
{
    const int t    = threadIdx.x;              // 0..127: owns cols [2t, 2t+1]
    const int g    = blockIdx.x;               // row group 0..63
    const int p    = blockIdx.y;               // plane (N*C)
    const int lane = threadIdx.x & 31;

    const int c0 = 2 * t;
    const float* xp = x + (size_t)p * IN_H * IN_W;
    float*       yp = y + (size_t)p * OUT_W * OUT_W;
    const int r0 = g * RPT;

    const bool edgeL = (lane == 0)  && (c0 >= 1);
    const bool edgeR = (lane == 31) && (c0 + 2 < IN_W);

    // raw row load (zero outside [0, IN_H)); e = cross-warp edge element
    auto loadraw = [&](int r, float& e) -> float2 {
        e = 0.f;
        if (r < 0 || r >= IN_H) return make_float2(0.f, 0.f);
        const float* row = xp + (size_t)r * IN_W;
        if (edgeL) e = __ldg(row + c0 - 1);
        if (edgeR) e = __ldg(row + c0 + 2);
        return *(const float2*)(row + c0);
    };

    // horizontal pre-combines: H = even phase, O = odd phase (2 columns)
    auto comb = [&](float2 c, float e,
                    float& H0, float& O0, float& H1, float& O1) {
        float l  = __shfl_up_sync(0xffffffffu, c.y, 1);   // col c0-1
        float rr = __shfl_down_sync(0xffffffffu, c.x, 1); // col c0+2
        if (lane == 0)  l  = e;
        if (lane == 31) rr = e;
        H0 = l   + 3.f * c.x;  O0 = 3.f * c.x + c.y;
        H1 = c.x + 3.f * c.y;  O1 = 3.f * c.y + rr;
    };

    // prologue: 3 loads issued back-to-back (r0-1, r0, r0+1)
    float ePr, eA, eB;
    float2 rPr = loadraw(r0 - 1, ePr);
    float2 rA  = loadraw(r0,     eA);   // consumed at i=0
    float2 rB  = loadraw(r0 + 1, eB);   // consumed at i=1

    float pH0, pO0, pH1, pO1;
    comb(rPr, ePr, pH0, pO0, pH1, pO1);

    #pragma unroll
    for (int i = 0; i <= RPT; i++) {
        const int r = r0 + i;

        // prefetch row r+2 FIRST (keeps 2 LDGs in flight)
        float eF = 0.f;
        float2 rF = make_float2(0.f, 0.f);
        if (i + 2 <= RPT) rF = loadraw(r + 2, eF);

        // combine current row (loaded 2 iterations ago)
        float cH0, cO0, cH1, cO1;
        comb(rA, eA, cH0, cO0, cH1, cO1);

        // output row 2r-1: vertical odd phase (3*prev + cur) * 1/16
        if (i > 0) {
            float4 v;
            v.x = (3.f * pH0 + cH0) * 0.0625f;
            v.y = (3.f * pO0 + cO0) * 0.0625f;
            v.z = (3.f * pH1 + cH1) * 0.0625f;
            v.w = (3.f * pO1 + cO1) * 0.0625f;
            *(float4*)(yp + (size_t)(2 * r - 1) * OUT_W + 2 * c0) = v;
        }
        // output row 2r: vertical even phase (prev + 3*cur) * 1/16
        if (i < RPT) {
            float4 v;
            v.x = (pH0 + 3.f * cH0) * 0.0625f;
            v.y = (pO0 + 3.f * cO0) * 0.0625f;
            v.z = (pH1 + 3.f * cH1) * 0.0625f;
            v.w = (pO1 + 3.f * cO1) * 0.0625f;
            *(float4*)(yp + (size_t)(2 * r) * OUT_W + 2 * c0) = v;
        }

        pH0 = cH0; pO0 = cO0; pH1 = cH1; pO1 = cO1;
        rA = rB; eA = eB;        // shift the 2-slot buffer
        rB = rF; eB = eF;
    }
}

extern "C" void kernel_launch(void* const* d_in, const int* in_sizes, int n_in,
                              void* d_out, int out_size)
{
    const float* x = (const float*)d_in[0];
    float* y = (float*)d_out;
    int planes = in_sizes[0] / (IN_H * IN_W);            // 512
    dim3 grid(IN_H / RPT, planes);                       // (64, 512)
    upscale2d_kernel<<<grid, 128>>>(x, y);
}

// round 15
// speedup vs baseline: 1.1140x; 1.0037x over previous
#include <cuda_runtime.h>

// Upscale2d: 2x zero-insert upsample + 4x4 binomial FIR == separable 2-tap
// polyphase: even (a + 3b)/4, odd (3b + c)/4 per axis.
// x: [8,64,256,256] f32 -> y: [8,64,512,512] f32, zero-padded borders.
//
// Continuing the winning direction (R13: smaller tiles -> fewer regs ->
// more resident warps -> higher DRAM duty): RPT=2, 128-thread CTAs,
// distance-2 pipelined float2 row loads (pipeline now spans the whole
// tile), shuffle horizontal combines, plain write-back float4 stores.
// Cross-tile boundary re-reads are L2 hits (input is L2-resident).

#define IN_H 256
#define IN_W 256
#define OUT_W 512
#define RPT 2   // input rows per thread

__global__ __launch_bounds__(128) void upscale2d_kernel(
    const float* __restrict__ x, float* __restrict__ y)
{
    const int t    = threadIdx.x;              // 0..127: owns cols [2t, 2t+1]
    const int g    = blockIdx.x;               // row group 0..127
    const int p    = blockIdx.y;               // plane (N*C)
    const int lane = threadIdx.x & 31;

    const int c0 = 2 * t;
    const float* xp = x + (size_t)p * IN_H * IN_W;
    float*       yp = y + (size_t)p * OUT_W * OUT_W;
    const int r0 = g * RPT;

    const bool edgeL = (lane == 0)  && (c0 >= 1);
    const bool edgeR = (lane == 31) && (c0 + 2 < IN_W);

    // raw row load (zero outside [0, IN_H)); e = cross-warp edge element
    auto loadraw = [&](int r, float& e) -> float2 {
        e = 0.f;
        if (r < 0 || r >= IN_H) return make_float2(0.f, 0.f);
        const float* row = xp + (size_t)r * IN_W;
        if (edgeL) e = __ldg(row + c0 - 1);
        if (edgeR) e = __ldg(row + c0 + 2);
        return *(const float2*)(row + c0);
    };

    // horizontal pre-combines: H = even phase, O = odd phase (2 columns)
    auto comb = [&](float2 c, float e,
                    float& H0, float& O0, float& H1, float& O1) {
        float l  = __shfl_up_sync(0xffffffffu, c.y, 1);   // col c0-1
        float rr = __shfl_down_sync(0xffffffffu, c.x, 1); // col c0+2
        if (lane == 0)  l  = e;
        if (lane == 31) rr = e;
        H0 = l   + 3.f * c.x;  O0 = 3.f * c.x + c.y;
        H1 = c.x + 3.f * c.y;  O1 = 3.f * c.y + rr;
    };

    // prologue: 3 loads issued back-to-back (r0-1, r0, r0+1)
    float ePr, eA, eB;
    float2 rPr = loadraw(r0 - 1, ePr);
    float2 rA  = loadraw(r0,     eA);   // consumed at i=0
    float2 rB  = loadraw(r0 + 1, eB);   // consumed at i=1

    float pH0, pO0, pH1, pO1;
    comb(rPr, ePr, pH0, pO0, pH1, pO1);

    #pragma unroll
    for (int i = 0; i <= RPT; i++) {
        const int r = r0 + i;

        // prefetch row r+2 FIRST (keeps 2 LDGs in flight)
        float eF = 0.f;
        float2 rF = make_float2(0.f, 0.f);
        if (i + 2 <= RPT) rF = loadraw(r + 2, eF);

        // combine current row (loaded 2 iterations ago)
        float cH0, cO0, cH1, cO1;
        comb(rA, eA, cH0, cO0, cH1, cO1);

        // output row 2r-1: vertical odd phase (3*prev + cur) * 1/16
        if (i > 0) {
            float4 v;
            v.x = (3.f * pH0 + cH0) * 0.0625f;
            v.y = (3.f * pO0 + cO0) * 0.0625f;
            v.z = (3.f * pH1 + cH1) * 0.0625f;
            v.w = (3.f * pO1 + cO1) * 0.0625f;
            *(float4*)(yp + (size_t)(2 * r - 1) * OUT_W + 2 * c0) = v;
        }
        // output row 2r: vertical even phase (prev + 3*cur) * 1/16
        if (i < RPT) {
            float4 v;
            v.x = (pH0 + 3.f * cH0) * 0.0625f;
            v.y = (pO0 + 3.f * cO0) * 0.0625f;
            v.z = (pH1 + 3.f * cH1) * 0.0625f;
            v.w = (pO1 + 3.f * cO1) * 0.0625f;
            *(float4*)(yp + (size_t)(2 * r) * OUT_W + 2 * c0) = v;
        }

        pH0 = cH0; pO0 = cO0; pH1 = cH1; pO1 = cO1;
        rA = rB; eA = eB;        // shift the 2-slot buffer
        rB = rF; eB = eF;
    }
}

extern "C" void kernel_launch(void* const* d_in, const int* in_sizes, int n_in,
                              void* d_out, int out_size)
{
    const float* x = (const float*)d_in[0];
    float* y = (float*)d_out;
    int planes = in_sizes[0] / (IN_H * IN_W);            // 512
    dim3 grid(IN_H / RPT, planes);                       // (128, 512)
    upscale2d_kernel<<<grid, 128>>>(x, y);
}